// round 10
// baseline (speedup 1.0000x reference)
#include <cuda_runtime.h>
#include <stdint.h>
#include <math.h>

static constexpr int BATCH  = 16;
static constexpr int C      = 128;
static constexpr int N      = 16384;
static constexpr int SPLITK = 16;
static constexpr int CHUNK  = N / SPLITK;    // 1024
static constexpr int NTILES = N / 128;       // 128
static constexpr size_t OUT_ELEMS = (size_t)BATCH * C * N;
static constexpr int LDS_ = 136;             // old-style padded stride (tail kernel)
static constexpr int AW = 68;                // uint2 per A smem row (136 words = 8 mod 32)
static constexpr int BW = 136;               // words per B smem row (136 = 8 mod 32)

// ---------------- scratch (static device globals; no allocations) ----------
__device__ float g_kg  [(size_t)BATCH * C * N];          // tf32 bit patterns
__device__ float g_v   [(size_t)BATCH * C * N];          // tf32 bit patterns
__device__ float g_part[(size_t)BATCH * SPLITK * C * C];
__device__ float g_fsum[(size_t)BATCH * NTILES * C];     // [b][tile][c]
__device__ float g_E   [(size_t)BATCH * C * C];
__device__ float g_F   [(size_t)BATCH * C * C];
__device__ float g_fb  [(size_t)BATCH * C];

__device__ __forceinline__ float sigmoidf_(float v) { return 1.0f / (1.0f + __expf(-v)); }

__device__ __forceinline__ uint32_t f2tf(float f) {
    uint32_t u; asm("cvt.rna.tf32.f32 %0, %1;" : "=r"(u) : "f"(f)); return u;
}
__device__ __forceinline__ float u2f(uint32_t u) { return __uint_as_float(u); }

__device__ __forceinline__ void mma_tf32(float c[4],
    uint32_t a0, uint32_t a1, uint32_t a2, uint32_t a3, uint32_t b0, uint32_t b1)
{
    asm volatile(
        "mma.sync.aligned.m16n8k8.row.col.f32.tf32.tf32.f32 "
        "{%0,%1,%2,%3}, {%4,%5,%6,%7}, {%8,%9}, {%0,%1,%2,%3};\n"
        : "+f"(c[0]), "+f"(c[1]), "+f"(c[2]), "+f"(c[3])
        : "r"(a0), "r"(a1), "r"(a2), "r"(a3), "r"(b0), "r"(b1));
}

__device__ __forceinline__ uint4 cvt4(float4 r) {
    return make_uint4(f2tf(r.x), f2tf(r.y), f2tf(r.z), f2tf(r.w));
}

// ======================= 64x64-warp-tile machinery (128 threads) ============
// A smem: uint2[8][AW]; pair (m, m+8) packed: pair index p(m) = (m>>4)*8 + (m&7),
// half = (m>>3)&1. Reader gets (a0,a1) / (a2,a3) with single LDS.64 each.
// B smem: uint32_t[8][BW], direct [k][n].

// A pair writer, f32 source (cvt): thread owns row m, writes k=0..7 of one slab.
__device__ __forceinline__ void wA_cvt(uint2 (*A)[AW], float4 u, float4 v, int m) {
    const int p = ((m >> 4) << 3) + (m & 7);
    uint32_t* w = (uint32_t*)&A[0][p] + ((m >> 3) & 1);
    const int S = 2 * AW;
    w[0 * S] = f2tf(u.x); w[1 * S] = f2tf(u.y); w[2 * S] = f2tf(u.z); w[3 * S] = f2tf(u.w);
    w[4 * S] = f2tf(v.x); w[5 * S] = f2tf(v.y); w[6 * S] = f2tf(v.z); w[7 * S] = f2tf(v.w);
}
// A pair writer, raw tf32 bits.
__device__ __forceinline__ void wA_raw(uint2 (*A)[AW], uint4 u, uint4 v, int m) {
    const int p = ((m >> 4) << 3) + (m & 7);
    uint32_t* w = (uint32_t*)&A[0][p] + ((m >> 3) & 1);
    const int S = 2 * AW;
    w[0 * S] = u.x; w[1 * S] = u.y; w[2 * S] = u.z; w[3 * S] = u.w;
    w[4 * S] = v.x; w[5 * S] = v.y; w[6 * S] = v.z; w[7 * S] = v.w;
}
// B direct writer (cvt): thread (kb, c) writes two uint4 at cols c*4 and c*4+64.
__device__ __forceinline__ void wB_dir(uint32_t (*B)[BW], float4 u, float4 v, int kb, int c) {
    *(uint4*)&B[kb][c * 4]      = cvt4(u);
    *(uint4*)&B[kb][c * 4 + 64] = cvt4(v);
}
// B transpose writer, raw bits (know): thread owns column d, writes k=0..7.
__device__ __forceinline__ void wB_tr_raw(uint32_t (*B)[BW], uint4 u, uint4 v, int d) {
    B[0][d] = u.x; B[1][d] = u.y; B[2][d] = u.z; B[3][d] = u.w;
    B[4][d] = v.x; B[5][d] = v.y; B[6][d] = v.z; B[7][d] = v.w;
}

// One 8-deep K-slab for a 64x64 warp tile (4 mfrag x 8 nfrag = 32 mma).
// Frag maps (m16n8k8 tf32): a0(g,tig) a1(g+8,tig) a2(g,tig+4) a3(g+8,tig+4);
// b0(tig,g) b1(tig+4,g); c0(g,2tig) c1(g,2tig+1) c2(g+8,2tig) c3(g+8,2tig+1).
__device__ __forceinline__ void compute64(const uint2 (*A)[AW], const uint32_t (*B)[BW],
                                          float acc[4][8][4], int warpM, int warpN,
                                          int g, int tig)
{
    uint32_t a[4][4], b[8][2];
#pragma unroll
    for (int mf = 0; mf < 4; mf++) {
        const int p = ((warpM * 4 + mf) << 3) + g;
        uint2 u1 = A[tig][p];
        uint2 u2 = A[tig + 4][p];
        a[mf][0] = u1.x; a[mf][1] = u1.y; a[mf][2] = u2.x; a[mf][3] = u2.y;
    }
#pragma unroll
    for (int nf = 0; nf < 8; nf++) {
        const int n = warpN * 64 + nf * 8 + g;
        b[nf][0] = B[tig][n]; b[nf][1] = B[tig + 4][n];
    }
#pragma unroll
    for (int mf = 0; mf < 4; mf++)
#pragma unroll
        for (int nf = 0; nf < 8; nf++)
            mma_tf32(acc[mf][nf], a[mf][0], a[mf][1], a[mf][2], a[mf][3],
                     b[nf][0], b[nf][1]);
}

// ---------------------------------------------------------------------------
// Kernel 1: fused projections. 128 threads, 4 warps (2x2), 128x128 tile.
// A virtual rows: group = m>>4 holds 8 channels; wi<8 -> value weight row,
// wi>=8 -> gate weight row (same channels) => value in c0/c1, gate in c2/c3.
// ---------------------------------------------------------------------------
__global__ void __launch_bounds__(128, 2)
proj_tc(const float* __restrict__ x,
        const float* __restrict__ Wk, const float* __restrict__ bk,
        const float* __restrict__ Wv, const float* __restrict__ bv,
        const float* __restrict__ Wg, const float* __restrict__ bg)
{
    __shared__ uint2    As[2][8][AW];
    __shared__ uint32_t Bs[2][8][BW];
    __shared__ float    red[64][2];

    const int idx   = blockIdx.x;
    const int type  = idx >> 1;
    const int cbase = (idx & 1) * 64;
    const int n0    = blockIdx.y << 7;
    const int b     = blockIdx.z;

    const float *W1, *W2, *b1, *b2;
    if (type == 0) { W1 = Wk; b1 = bk; W2 = Wg + C * C; b2 = bg + C; }
    else           { W1 = Wv; b1 = bv; W2 = Wg;         b2 = bg;     }

    const int tid = threadIdx.x, lane = tid & 31, warp = tid >> 5;
    const int g = lane >> 2, tig = lane & 3;
    const int warpM = warp & 1, warpN = warp >> 1;

    // A loader: thread owns virtual row m = tid
    const int m  = tid;
    const int wi = m & 15;
    const int ch = cbase + ((m >> 4) << 3) + (wi & 7);
    const float* aptr = ((wi < 8) ? W1 : W2) + (size_t)ch * C;
    // B loader: thread (kb, cc)
    const float* xb = x + (size_t)b * C * N;
    const int kb = tid >> 4, cc = tid & 15;
    const float* bptr = xb + (size_t)kb * N + n0 + cc * 4;

    float4 au = *(const float4*)(aptr);
    float4 av = *(const float4*)(aptr + 4);
    float4 bu = *(const float4*)(bptr);
    float4 bv4 = *(const float4*)(bptr + 64);
    wA_cvt(As[0], au, av, m); wB_dir(Bs[0], bu, bv4, kb, cc);
    __syncthreads();

    float acc[4][8][4] = {};
#pragma unroll 1
    for (int s = 0; s < 16; s++) {
        const int cur = s & 1;
        if (s < 15) {
            au  = *(const float4*)(aptr + (s + 1) * 8);
            av  = *(const float4*)(aptr + (s + 1) * 8 + 4);
            bu  = *(const float4*)(bptr + (size_t)(s + 1) * 8 * N);
            bv4 = *(const float4*)(bptr + (size_t)(s + 1) * 8 * N + 64);
        }
        compute64(As[cur], Bs[cur], acc, warpM, warpN, g, tig);
        if (s < 15) {
            wA_cvt(As[cur ^ 1], au, av, m); wB_dir(Bs[cur ^ 1], bu, bv4, kb, cc);
            __syncthreads();
        }
    }

    if (type == 0) {
#pragma unroll
        for (int mf = 0; mf < 4; mf++) {
            const int chn = cbase + (warpM * 4 + mf) * 8 + g;
            const float bb1 = b1[chn], bb2 = b2[chn];
            float* dst = g_kg + ((size_t)b * C + chn) * N + n0 + warpN * 64 + 2 * tig;
#pragma unroll
            for (int nf = 0; nf < 8; nf++) {
                float o0 = (acc[mf][nf][0] + bb1) * sigmoidf_(acc[mf][nf][2] + bb2);
                float o1 = (acc[mf][nf][1] + bb1) * sigmoidf_(acc[mf][nf][3] + bb2);
                *(float2*)(dst + nf * 8) = make_float2(u2f(f2tf(o0)), u2f(f2tf(o1)));
            }
        }
    } else {
#pragma unroll
        for (int mf = 0; mf < 4; mf++) {
            const int chn = cbase + (warpM * 4 + mf) * 8 + g;
            const float bb1 = b1[chn], bb2 = b2[chn];
            float* dv = g_v + ((size_t)b * C + chn) * N + n0 + warpN * 64 + 2 * tig;
            float sm = 0.f;
#pragma unroll
            for (int nf = 0; nf < 8; nf++) {
                float o0 = acc[mf][nf][0] + bb1;
                float o1 = acc[mf][nf][1] + bb1;
                *(float2*)(dv + nf * 8) = make_float2(u2f(f2tf(o0)), u2f(f2tf(o1)));
                sm += sigmoidf_(acc[mf][nf][2] + bb2) + sigmoidf_(acc[mf][nf][3] + bb2);
            }
            sm += __shfl_xor_sync(0xffffffffu, sm, 1);
            sm += __shfl_xor_sync(0xffffffffu, sm, 2);
            if (tig == 0) red[(warpM * 4 + mf) * 8 + g][warpN] = sm;
        }
        __syncthreads();
        if (tid < 64)
            g_fsum[((size_t)b * NTILES + blockIdx.y) * C + cbase + tid] =
                red[tid][0] + red[tid][1];
    }
}

// ---------------------------------------------------------------------------
// Kernel 2: knowledge partials (NT GEMM), raw tf32 bits, 128 threads.
// ---------------------------------------------------------------------------
__global__ void __launch_bounds__(128, 2)
know_tc()
{
    __shared__ uint2    As[2][8][AW];
    __shared__ uint32_t Bs[2][8][BW];

    const int s = blockIdx.x, b = blockIdx.y;
    const int tid = threadIdx.x, lane = tid & 31, warp = tid >> 5;
    const int g = lane >> 2, tig = lane & 3;
    const int warpM = warp & 1, warpN = warp >> 1;

    const float* arow = g_kg + ((size_t)b * C + tid) * N + (size_t)s * CHUNK;
    const float* brow = g_v  + ((size_t)b * C + tid) * N + (size_t)s * CHUNK;

    uint4 au = *(const uint4*)(arow), av = *(const uint4*)(arow + 4);
    uint4 bu = *(const uint4*)(brow), bv4 = *(const uint4*)(brow + 4);
    wA_raw(As[0], au, av, tid); wB_tr_raw(Bs[0], bu, bv4, tid);
    __syncthreads();

    float acc[4][8][4] = {};
#pragma unroll 1
    for (int ss = 0; ss < CHUNK / 8; ss++) {
        const int cur = ss & 1;
        if (ss < CHUNK / 8 - 1) {
            au  = *(const uint4*)(arow + (ss + 1) * 8);
            av  = *(const uint4*)(arow + (ss + 1) * 8 + 4);
            bu  = *(const uint4*)(brow + (ss + 1) * 8);
            bv4 = *(const uint4*)(brow + (ss + 1) * 8 + 4);
        }
        compute64(As[cur], Bs[cur], acc, warpM, warpN, g, tig);
        if (ss < CHUNK / 8 - 1) {
            wA_raw(As[cur ^ 1], au, av, tid); wB_tr_raw(Bs[cur ^ 1], bu, bv4, tid);
            __syncthreads();
        }
    }

    float* dst = g_part + ((size_t)b * SPLITK + s) * C * C;
#pragma unroll
    for (int mf = 0; mf < 4; mf++) {
        const int row = warpM * 64 + mf * 16 + g;
#pragma unroll
        for (int nf = 0; nf < 8; nf++) {
            const int col = warpN * 64 + nf * 8 + 2 * tig;
            *(float2*)(dst + (size_t)row * C + col)       = make_float2(acc[mf][nf][0], acc[mf][nf][1]);
            *(float2*)(dst + (size_t)(row + 8) * C + col) = make_float2(acc[mf][nf][2], acc[mf][nf][3]);
        }
    }
}

// ============== old-style 64x32 helpers (kept for the small tail kernel) ====
__device__ __forceinline__ void stsT(uint32_t (*S)[LDS_], float4 r, int tid) {
    const int m = tid >> 1, ko = (tid & 1) << 2;
    S[ko + 0][m] = f2tf(r.x); S[ko + 1][m] = f2tf(r.y);
    S[ko + 2][m] = f2tf(r.z); S[ko + 3][m] = f2tf(r.w);
}
__device__ __forceinline__ void stsD(uint32_t (*S)[LDS_], float4 r, int tid) {
    const int kb = tid >> 5, nb = (tid & 31) << 2;
    *(uint4*)&S[kb][nb] = cvt4(r);
}
__device__ __forceinline__ void compute_slab8(const uint32_t (*As)[LDS_], const uint32_t (*Bs)[LDS_],
                                              float acc[4][4][4], int mrow, int ncol, int g, int tig)
{
    uint32_t a[4][4], b[4][2];
#pragma unroll
    for (int mf = 0; mf < 4; mf++) {
        const int m = mrow + mf * 16 + g;
        a[mf][0] = As[tig][m];     a[mf][1] = As[tig][m + 8];
        a[mf][2] = As[tig + 4][m]; a[mf][3] = As[tig + 4][m + 8];
    }
#pragma unroll
    for (int nf = 0; nf < 4; nf++) {
        const int n = ncol + nf * 8 + g;
        b[nf][0] = Bs[tig][n]; b[nf][1] = Bs[tig + 4][n];
    }
#pragma unroll
    for (int mf = 0; mf < 4; mf++)
#pragma unroll
        for (int nf = 0; nf < 4; nf++)
            mma_tf32(acc[mf][nf], a[mf][0], a[mf][1], a[mf][2], a[mf][3],
                     b[nf][0], b[nf][1]);
}

// ---------------------------------------------------------------------------
// Kernel 3 (fused tail): per batch block (256 threads):
//   fs = mean(sig(forget)); M = fs*prev + sum(partials) -> d_out tail;
//   E = Wp*M^T; F = E*Wq; fb = E*bq + bp.
// ---------------------------------------------------------------------------
__global__ void __launch_bounds__(256, 2)
tail_tc(const float* __restrict__ prev, const float* __restrict__ Wp,
        const float* __restrict__ Wq, const float* __restrict__ bq,
        const float* __restrict__ bp, float* __restrict__ dout)
{
    __shared__ uint32_t As[2][8][LDS_];
    __shared__ uint32_t Bs[2][8][LDS_];
    __shared__ float fs[128];

    const int b = blockIdx.x;
    const int tid = threadIdx.x, lane = tid & 31, warp = tid >> 5;
    const int g = lane >> 2, tig = lane & 3;
    const int warpM = warp & 1, warpN = warp >> 1;
    const int mrow = warpM * 64, ncol = warpN * 32;

    if (tid < 128) {
        const float* p = g_fsum + (size_t)b * NTILES * C + tid;
        float sm = 0.f;
        for (int i = 0; i < NTILES; i++) sm += p[(size_t)i * C];
        fs[tid] = sm * (1.0f / (float)N);
    }
    __syncthreads();

    float* M = dout + OUT_ELEMS + (size_t)b * C * C;
    for (int e = tid; e < C * C; e += 256) {
        const int c = e >> 7;
        float a = fs[c] * prev[(size_t)b * C * C + e];
#pragma unroll
        for (int s2 = 0; s2 < SPLITK; s2++)
            a += g_part[((size_t)b * SPLITK + s2) * C * C + e];
        M[e] = a;
    }
    __syncthreads();

    // E = Wp * M^T
    {
        const int am = tid >> 1;
        const float* aptr = Wp + (size_t)am * C + ((tid & 1) << 2);
        const float* bptr = M  + (size_t)am * C + ((tid & 1) << 2);
        float4 ra = *(const float4*)aptr;
        float4 rb = *(const float4*)bptr;
        stsT(As[0], ra, tid); stsT(Bs[0], rb, tid);
        __syncthreads();
        float acc[4][4][4] = {};
#pragma unroll 1
        for (int s = 0; s < 16; s++) {
            const int cur = s & 1;
            if (s < 15) {
                ra = *(const float4*)(aptr + (s + 1) * 8);
                rb = *(const float4*)(bptr + (s + 1) * 8);
            }
            compute_slab8(As[cur], Bs[cur], acc, mrow, ncol, g, tig);
            if (s < 15) { stsT(As[cur ^ 1], ra, tid); stsT(Bs[cur ^ 1], rb, tid); __syncthreads(); }
        }
        float* dst = g_E + (size_t)b * C * C;
#pragma unroll
        for (int mf = 0; mf < 4; mf++) {
            const int row = mrow + mf * 16 + g;
#pragma unroll
            for (int nf = 0; nf < 4; nf++) {
                const int col = ncol + nf * 8 + 2 * tig;
                *(float2*)(dst + (size_t)row * C + col)       = make_float2(acc[mf][nf][0], acc[mf][nf][1]);
                *(float2*)(dst + (size_t)(row + 8) * C + col) = make_float2(acc[mf][nf][2], acc[mf][nf][3]);
            }
        }
    }
    __syncthreads();

    // F = E * Wq ; fb
    {
        const float* E = g_E + (size_t)b * C * C;
        const int am = tid >> 1;
        const float* aptr = E + (size_t)am * C + ((tid & 1) << 2);
        const float* bptr = Wq + (size_t)(tid >> 5) * C + ((tid & 31) << 2);
        float4 ra = *(const float4*)aptr;
        float4 rb = *(const float4*)bptr;
        stsT(As[0], ra, tid); stsD(Bs[0], rb, tid);
        __syncthreads();
        float acc[4][4][4] = {};
#pragma unroll 1
        for (int s = 0; s < 16; s++) {
            const int cur = s & 1;
            if (s < 15) {
                ra = *(const float4*)(aptr + (s + 1) * 8);
                rb = *(const float4*)(bptr + (size_t)(s + 1) * 8 * C);
            }
            compute_slab8(As[cur], Bs[cur], acc, mrow, ncol, g, tig);
            if (s < 15) { stsT(As[cur ^ 1], ra, tid); stsD(Bs[cur ^ 1], rb, tid); __syncthreads(); }
        }
        float* dst = g_F + (size_t)b * C * C;
#pragma unroll
        for (int mf = 0; mf < 4; mf++) {
            const int row = mrow + mf * 16 + g;
#pragma unroll
            for (int nf = 0; nf < 4; nf++) {
                const int col = ncol + nf * 8 + 2 * tig;
                *(float2*)(dst + (size_t)row * C + col)       = make_float2(acc[mf][nf][0], acc[mf][nf][1]);
                *(float2*)(dst + (size_t)(row + 8) * C + col) = make_float2(acc[mf][nf][2], acc[mf][nf][3]);
            }
        }
        __syncthreads();
        if (tid < 128) {
            float sm = bp[tid];
            const float* er = E + (size_t)tid * C;
            for (int c = 0; c < C; c++) sm = fmaf(er[c], bq[c], sm);
            g_fb[(size_t)b * C + tid] = sm;
        }
    }
}

// ---------------------------------------------------------------------------
// Kernel 4: out = F*x + fb + x. 128 threads, 64x64 warp tiles.
// ---------------------------------------------------------------------------
__global__ void __launch_bounds__(128, 2)
out_tc(const float* __restrict__ x, float* __restrict__ dout)
{
    __shared__ uint2    As[2][8][AW];
    __shared__ uint32_t Bs[2][8][BW];

    const int n0 = blockIdx.x << 7;
    const int b  = blockIdx.y;
    const float* xb = x + (size_t)b * C * N;

    const int tid = threadIdx.x, lane = tid & 31, warp = tid >> 5;
    const int g = lane >> 2, tig = lane & 3;
    const int warpM = warp & 1, warpN = warp >> 1;

    const float* aptr = g_F + (size_t)b * C * C + (size_t)tid * C;
    const int kb = tid >> 4, cc = tid & 15;
    const float* bptr = xb + (size_t)kb * N + n0 + cc * 4;

    float4 au = *(const float4*)(aptr);
    float4 av = *(const float4*)(aptr + 4);
    float4 bu = *(const float4*)(bptr);
    float4 bv4 = *(const float4*)(bptr + 64);
    wA_cvt(As[0], au, av, tid); wB_dir(Bs[0], bu, bv4, kb, cc);
    __syncthreads();

    float acc[4][8][4] = {};
#pragma unroll 1
    for (int s = 0; s < 16; s++) {
        const int cur = s & 1;
        if (s < 15) {
            au  = *(const float4*)(aptr + (s + 1) * 8);
            av  = *(const float4*)(aptr + (s + 1) * 8 + 4);
            bu  = *(const float4*)(bptr + (size_t)(s + 1) * 8 * N);
            bv4 = *(const float4*)(bptr + (size_t)(s + 1) * 8 * N + 64);
        }
        compute64(As[cur], Bs[cur], acc, warpM, warpN, g, tig);
        if (s < 15) {
            wA_cvt(As[cur ^ 1], au, av, tid); wB_dir(Bs[cur ^ 1], bu, bv4, kb, cc);
            __syncthreads();
        }
    }

#pragma unroll
    for (int mf = 0; mf < 4; mf++) {
        const int o = warpM * 64 + mf * 16 + g;
        const float fb0 = g_fb[(size_t)b * C + o];
        const float fb1 = g_fb[(size_t)b * C + o + 8];
#pragma unroll
        for (int nf = 0; nf < 8; nf++) {
            const int col = n0 + warpN * 64 + nf * 8 + 2 * tig;
            float2 r0 = *(const float2*)(xb + (size_t)o * N + col);
            float2 r1 = *(const float2*)(xb + (size_t)(o + 8) * N + col);
            *(float2*)(dout + ((size_t)b * C + o) * N + col) =
                make_float2(acc[mf][nf][0] + fb0 + r0.x, acc[mf][nf][1] + fb0 + r0.y);
            *(float2*)(dout + ((size_t)b * C + o + 8) * N + col) =
                make_float2(acc[mf][nf][2] + fb1 + r1.x, acc[mf][nf][3] + fb1 + r1.y);
        }
    }
}

// ---------------------------------------------------------------------------
extern "C" void kernel_launch(void* const* d_in, const int* in_sizes, int n_in,
                              void* d_out, int out_size)
{
    const float* x    = (const float*)d_in[0];
    const float* prev = (const float*)d_in[1];
    const float* Wq   = (const float*)d_in[2];
    const float* bq   = (const float*)d_in[3];
    const float* Wk   = (const float*)d_in[4];
    const float* bk   = (const float*)d_in[5];
    const float* Wv   = (const float*)d_in[6];
    const float* bv   = (const float*)d_in[7];
    const float* Wg   = (const float*)d_in[8];
    const float* bg   = (const float*)d_in[9];
    const float* Wp   = (const float*)d_in[10];
    const float* bp   = (const float*)d_in[11];
    float* out = (float*)d_out;

    proj_tc<<<dim3(4, NTILES, BATCH), 128>>>(x, Wk, bk, Wv, bv, Wg, bg);
    know_tc<<<dim3(SPLITK, BATCH), 128>>>();
    tail_tc<<<BATCH, 256>>>(prev, Wp, Wq, bq, bp, out);
    out_tc<<<dim3(NTILES, BATCH), 128>>>(x, out);
}